// round 6
// baseline (speedup 1.0000x reference)
#include <cuda_runtime.h>
#include <math.h>
#include <stdint.h>

// ---------------- problem constants ----------------
#define NODES   100000
#define EDGESMX 1600000
#define UNITS   256
#define TSTEPS  18
#define FIN     8
#define FT      144            // FIN * TSTEPS
#define NH      (NODES*UNITS)
#define KBR     264            // folded K rows (256 H + 8 AX)

// ---------------- device scratch ----------------
__device__ __align__(16) float g_deg [NODES];
__device__ __align__(16) float g_norm[EDGESMX];
__device__ __align__(16) float g_AX[(size_t)NODES * FT];
__device__ __align__(16) float g_H [(size_t)NH];
__device__ __align__(16) float g_Z [(size_t)NH];
__device__ __align__(16) float g_HR[(size_t)NH];
__device__ __align__(16) float g_acc[(size_t)NH];
// 3xTF32-split folded weights (hi = tf32(v), lo = tf32(v-hi))
__device__ __align__(16) float g_Bzr_hi[KBR * 512];
__device__ __align__(16) float g_Bzr_lo[KBR * 512];
__device__ __align__(16) float g_Bh_hi [KBR * 256];
__device__ __align__(16) float g_Bh_lo [KBR * 256];
__device__ __align__(16) float g_Bm_hi [3 * 256 * 256];
__device__ __align__(16) float g_Bm_lo [3 * 256 * 256];
__device__ __align__(16) float g_czr[512];
__device__ __align__(16) float g_ch [256];
__device__ __align__(16) float g_probs[TSTEPS];
__device__ int g_is64;

// ---------------- tf32 helpers ----------------
__device__ __forceinline__ uint32_t f2tf(float f) {
    uint32_t r; asm("cvt.rna.tf32.f32 %0, %1;" : "=r"(r) : "f"(f)); return r;
}
__device__ __forceinline__ void split_tf(float v, uint32_t& hi, uint32_t& lo) {
    hi = f2tf(v);
    lo = f2tf(v - __uint_as_float(hi));
}

__device__ __forceinline__ int edge_at(const void* ei, long long i) {
    if (g_is64) return (int)((const long long*)ei)[i];
    return ((const int*)ei)[i];
}

// ---------------- setup kernels ----------------
// init H/acc/deg + edge dtype probe (int64 LE < 2^31 -> odd int32 slots are 0)
__global__ void k_init(const int* __restrict__ ei32, int n, int nh) {
    int i = blockIdx.x * blockDim.x + threadIdx.x;
    if (i == 0) {
        int is64 = 1;
        for (int q = 1; q < 64; q += 2)
            if (ei32[q] != 0) { is64 = 0; break; }
        g_is64 = is64;
    }
    if (i < nh) { g_H[i] = 0.f; g_acc[i] = 0.f; }
    if (i < n)  g_deg[i] = 1.0f;   // self-loop weight
}

__global__ void k_deg(const void* __restrict__ ei, const float* __restrict__ w, int E) {
    int e = blockIdx.x * blockDim.x + threadIdx.x;
    if (e < E) atomicAdd(&g_deg[edge_at(ei, (long long)E + e)], w[e]);
}

// fused: edge norms (idx < E) + AX self-loop init (idx >= E)
__global__ void k_normax(const float* __restrict__ x, const void* __restrict__ ei,
                         const float* __restrict__ w, int E, int n) {
    int idx = blockIdx.x * blockDim.x + threadIdx.x;
    if (idx < E) {
        int s = edge_at(ei, idx);
        int d = edge_at(ei, (long long)E + idx);
        g_norm[idx] = rsqrtf(g_deg[s]) * w[idx] * rsqrtf(g_deg[d]);
    } else {
        int j2 = idx - E;
        if (j2 >= n * 36) return;
        int node = j2 / 36, j = j2 % 36;
        float r = rsqrtf(g_deg[node]); float c = r * r;
        const float4 xv = *reinterpret_cast<const float4*>(&x[(size_t)node * FT + j * 4]);
        float4 o = make_float4(c*xv.x, c*xv.y, c*xv.z, c*xv.w);
        *reinterpret_cast<float4*>(&g_AX[(size_t)node * FT + j * 4]) = o;
    }
}

__global__ void k_axedge(const float* __restrict__ x, const void* __restrict__ ei, int E) {
    long long idx = (long long)blockIdx.x * blockDim.x + threadIdx.x;
    if (idx >= (long long)E * 36) return;
    int e = (int)(idx / 36), j = (int)(idx % 36);
    int s = edge_at(ei, e);
    int d = edge_at(ei, (long long)E + e);
    float c = g_norm[e];
    const float4 xv = *reinterpret_cast<const float4*>(&x[(size_t)s * FT + j * 4]);
    float* p = &g_AX[(size_t)d * FT + j * 4];
    asm volatile("red.global.add.v4.f32 [%0], {%1,%2,%3,%4};"
                 :: "l"(__cvta_generic_to_global(p)),
                    "f"(c*xv.x), "f"(c*xv.y), "f"(c*xv.z), "f"(c*xv.w)
                 : "memory");
}

__global__ void k_probs(const float* __restrict__ att) {
    if (threadIdx.x == 0) {
        float mx = -1e30f;
        for (int i = 0; i < TSTEPS; i++) mx = fmaxf(mx, att[i]);
        float s = 0.f, e[TSTEPS];
        for (int i = 0; i < TSTEPS; i++) { e[i] = expf(att[i] - mx); s += e[i]; }
        float inv = 1.f / s;
        for (int i = 0; i < TSTEPS; i++) g_probs[i] = e[i] * inv;
    }
}

// Fold gconv into gate linear; write tf32 hi/lo split. Output selected on device.
__global__ void k_buildB(const float* __restrict__ Wg, const float* __restrict__ Wl,
                         const float* __restrict__ bg, const float* __restrict__ bl,
                         int which) {
    float* Bhi = (which == 2) ? g_Bh_hi : g_Bzr_hi;
    float* Blo = (which == 2) ? g_Bh_lo : g_Bzr_lo;
    float* cout = (which == 2) ? g_ch : g_czr;
    const int ldb    = (which == 2) ? 256 : 512;
    const int coloff = (which == 1) ? 256 : 0;

    int idx = blockIdx.x * blockDim.x + threadIdx.x;
    if (idx >= 265 * 256) return;
    int k = idx >> 8, n = idx & 255;
    float v;
    if (k < 256) {
        v = Wl[(size_t)(256 + k) * 256 + n];
    } else if (k < 264) {
        int f = k - 256;
        float s = 0.f;
        for (int i = 0; i < 256; i++) s += Wg[f * 256 + i] * Wl[(size_t)i * 256 + n];
        v = s;
    } else {
        float s = bl[n];
        for (int i = 0; i < 256; i++) s += bg[i] * Wl[(size_t)i * 256 + n];
        cout[coloff + n] = s;
        return;
    }
    uint32_t hi, lo; split_tf(v, hi, lo);
    Bhi[(size_t)k * ldb + coloff + n] = __uint_as_float(hi);
    Blo[(size_t)k * ldb + coloff + n] = __uint_as_float(lo);
}

// Split MLP weights (3 x 256x256) into hi/lo
__global__ void k_splitW(const float* __restrict__ W1, const float* __restrict__ W2,
                         const float* __restrict__ W3) {
    int idx = blockIdx.x * blockDim.x + threadIdx.x;
    if (idx >= 3 * 65536) return;
    int which = idx >> 16, r = idx & 65535;
    const float* W = (which == 0) ? W1 : (which == 1) ? W2 : W3;
    uint32_t hi, lo; split_tf(W[r], hi, lo);
    g_Bm_hi[idx] = __uint_as_float(hi);
    g_Bm_lo[idx] = __uint_as_float(lo);
}

// ---------------- 3xTF32 tensor-core GEMM, double-buffered, fused epilogues ----------------
// modes:
//  0: [H | AX_t] @ Bzr + czr -> sigmoid; n<256: g_Z, n>=256: g_HR = s*H
//  1: [HR| AX_t] @ Bh  + ch  -> tanh; GRU update g_H, g_acc += p_t*Hn
//  2: relu(g_acc) @ Bm0 + b -> relu -> g_Z
//  3: g_Z         @ Bm1 + b -> relu -> g_HR
//  4: g_HR        @ Bm2 + b -> relu -> g_Z
#define BMt 128
#define BNt 128
#define BKt 8
#define TLD 132   // padded leading dim (k-major tiles)

__device__ __forceinline__ void mma_tf32(float c[4], const uint32_t a[4], const uint32_t b[2]) {
    asm volatile(
        "mma.sync.aligned.m16n8k8.row.col.f32.tf32.tf32.f32 "
        "{%0,%1,%2,%3}, {%4,%5,%6,%7}, {%8,%9}, {%0,%1,%2,%3};\n"
        : "+f"(c[0]), "+f"(c[1]), "+f"(c[2]), "+f"(c[3])
        : "r"(a[0]), "r"(a[1]), "r"(a[2]), "r"(a[3]), "r"(b[0]), "r"(b[1]));
}

__global__ __launch_bounds__(256, 2)
void gemm_tc(const float* __restrict__ biasp, int M, int N, int mode, int t) {
    const float* A = (mode == 0) ? g_H : (mode == 1) ? g_HR
                   : (mode == 2) ? g_acc : (mode == 3) ? g_Z : g_HR;
    const float* Bhi; const float* Blo;
    if      (mode == 0) { Bhi = g_Bzr_hi; Blo = g_Bzr_lo; }
    else if (mode == 1) { Bhi = g_Bh_hi;  Blo = g_Bh_lo;  }
    else { Bhi = g_Bm_hi + (size_t)(mode - 2) * 65536; Blo = g_Bm_lo + (size_t)(mode - 2) * 65536; }
    const float* bias = (mode == 0) ? g_czr : (mode == 1) ? g_ch : biasp;
    const bool useAX = (mode <= 1);
    const bool reluA = (mode == 2);

    __shared__ uint32_t AsH[2][BKt][TLD];
    __shared__ uint32_t AsL[2][BKt][TLD];
    __shared__ uint32_t BsH[2][BKt][TLD];
    __shared__ uint32_t BsL[2][BKt][TLD];

    const int tid = threadIdx.x, lane = tid & 31, wid = tid >> 5;
    const int wm = (wid & 1) * 64;
    const int wn = (wid >> 1) * 32;
    const int g = lane >> 2, tg = lane & 3;
    const int bn = blockIdx.x * BNt, bm = blockIdx.y * BMt;   // x = n-tile (L2 reuse of A)

    const int aRow = tid >> 1, aCol = (tid & 1) * 4;   // A tile: 128 x 8, 1 float4/thread
    const int bRow = tid >> 5, bCol = lane * 4;        // B tile: 8 x 128, 1 float4/thread
    const int m = bm + aRow;

    float c[4][4][4];
#pragma unroll
    for (int i = 0; i < 4; i++)
#pragma unroll
        for (int j = 0; j < 4; j++)
#pragma unroll
            for (int q = 0; q < 4; q++) c[i][j][q] = 0.f;

    const int nT = useAX ? 33 : 32;

    // ---- helpers (lambdas keep code compact) ----
    auto loadA = [&](int kt, float4& va) {
        if (kt < 32) {
            va = make_float4(0.f, 0.f, 0.f, 0.f);
            if (m < M) va = *reinterpret_cast<const float4*>(&A[(size_t)m * 256 + kt * BKt + aCol]);
            if (reluA) { va.x = fmaxf(va.x, 0.f); va.y = fmaxf(va.y, 0.f);
                         va.z = fmaxf(va.z, 0.f); va.w = fmaxf(va.w, 0.f); }
        } else { // AX tile: k rows 0..7 = features
            float v0 = 0.f, v1 = 0.f, v2 = 0.f, v3 = 0.f;
            if (m < M) {
                const float* ax = &g_AX[(size_t)m * FT + aCol * TSTEPS + t];
                v0 = ax[0]; v1 = ax[TSTEPS]; v2 = ax[2 * TSTEPS]; v3 = ax[3 * TSTEPS];
            }
            va = make_float4(v0, v1, v2, v3);
        }
    };
    auto loadB = [&](int kt, float4& vh, float4& vl) {
        size_t off = (size_t)(kt * BKt + bRow) * N + bn + bCol;
        vh = *reinterpret_cast<const float4*>(&Bhi[off]);
        vl = *reinterpret_cast<const float4*>(&Blo[off]);
    };
    auto storeTile = [&](int buf, const float4& va, const float4& vh, const float4& vl) {
        uint32_t h, l;
        split_tf(va.x, h, l); AsH[buf][aCol + 0][aRow] = h; AsL[buf][aCol + 0][aRow] = l;
        split_tf(va.y, h, l); AsH[buf][aCol + 1][aRow] = h; AsL[buf][aCol + 1][aRow] = l;
        split_tf(va.z, h, l); AsH[buf][aCol + 2][aRow] = h; AsL[buf][aCol + 2][aRow] = l;
        split_tf(va.w, h, l); AsH[buf][aCol + 3][aRow] = h; AsL[buf][aCol + 3][aRow] = l;
        BsH[buf][bRow][bCol + 0] = __float_as_uint(vh.x);
        BsH[buf][bRow][bCol + 1] = __float_as_uint(vh.y);
        BsH[buf][bRow][bCol + 2] = __float_as_uint(vh.z);
        BsH[buf][bRow][bCol + 3] = __float_as_uint(vh.w);
        BsL[buf][bRow][bCol + 0] = __float_as_uint(vl.x);
        BsL[buf][bRow][bCol + 1] = __float_as_uint(vl.y);
        BsL[buf][bRow][bCol + 2] = __float_as_uint(vl.z);
        BsL[buf][bRow][bCol + 3] = __float_as_uint(vl.w);
    };

    // prologue: stage tile 0
    {
        float4 va, vh, vl;
        loadA(0, va); loadB(0, vh, vl);
        storeTile(0, va, vh, vl);
    }
    __syncthreads();

    for (int kt = 0; kt < nT; kt++) {
        const int cur = kt & 1, nxt = cur ^ 1;
        float4 va, vh, vl;
        const bool pf = (kt + 1 < nT);
        if (pf) { loadA(kt + 1, va); loadB(kt + 1, vh, vl); }

        // compute on cur
        uint32_t bh[4][2], bl[4][2];
#pragma unroll
        for (int ni = 0; ni < 4; ni++) {
            int n0 = wn + ni * 8;
            bh[ni][0] = BsH[cur][tg][n0 + g];
            bh[ni][1] = BsH[cur][tg + 4][n0 + g];
            bl[ni][0] = BsL[cur][tg][n0 + g];
            bl[ni][1] = BsL[cur][tg + 4][n0 + g];
        }
#pragma unroll
        for (int mi = 0; mi < 4; mi++) {
            int m0 = wm + mi * 16;
            uint32_t ah[4], al[4];
            ah[0] = AsH[cur][tg][m0 + g];     ah[1] = AsH[cur][tg][m0 + g + 8];
            ah[2] = AsH[cur][tg + 4][m0 + g]; ah[3] = AsH[cur][tg + 4][m0 + g + 8];
            al[0] = AsL[cur][tg][m0 + g];     al[1] = AsL[cur][tg][m0 + g + 8];
            al[2] = AsL[cur][tg + 4][m0 + g]; al[3] = AsL[cur][tg + 4][m0 + g + 8];
#pragma unroll
            for (int ni = 0; ni < 4; ni++) {
                mma_tf32(c[mi][ni], ah, bl[ni]);
                mma_tf32(c[mi][ni], al, bh[ni]);
                mma_tf32(c[mi][ni], ah, bh[ni]);
            }
        }

        if (pf) storeTile(nxt, va, vh, vl);
        __syncthreads();
    }

    // ---- fused epilogue ----
    const float pt = (mode == 1) ? g_probs[t] : 0.f;
#pragma unroll
    for (int mi = 0; mi < 4; mi++) {
        int r0 = bm + wm + mi * 16 + g;
#pragma unroll
        for (int half = 0; half < 2; half++) {
            int r = r0 + half * 8;
            if (r >= M) continue;
            size_t base = (size_t)r * 256;
#pragma unroll
            for (int ni = 0; ni < 4; ni++) {
                int n = bn + wn + ni * 8 + tg * 2;
                float v0 = c[mi][ni][half * 2 + 0] + bias[n];
                float v1 = c[mi][ni][half * 2 + 1] + bias[n + 1];
                if (mode == 0) {
                    float s0 = 1.f / (1.f + expf(-v0));
                    float s1 = 1.f / (1.f + expf(-v1));
                    if (n < 256) {
                        g_Z[base + n] = s0; g_Z[base + n + 1] = s1;
                    } else {
                        int n2 = n - 256;
                        g_HR[base + n2]     = s0 * g_H[base + n2];
                        g_HR[base + n2 + 1] = s1 * g_H[base + n2 + 1];
                    }
                } else if (mode == 1) {
                    float h0 = tanhf(v0), h1 = tanhf(v1);
                    float z0 = g_Z[base + n], z1 = g_Z[base + n + 1];
                    float o0 = g_H[base + n], o1 = g_H[base + n + 1];
                    float hn0 = z0 * o0 + (1.f - z0) * h0;
                    float hn1 = z1 * o1 + (1.f - z1) * h1;
                    g_H[base + n] = hn0; g_H[base + n + 1] = hn1;
                    g_acc[base + n]     += pt * hn0;
                    g_acc[base + n + 1] += pt * hn1;
                } else {
                    float r0v = fmaxf(v0, 0.f), r1v = fmaxf(v1, 0.f);
                    if (mode == 3) { g_HR[base + n] = r0v; g_HR[base + n + 1] = r1v; }
                    else           { g_Z [base + n] = r0v; g_Z [base + n + 1] = r1v; }
                }
            }
        }
    }
}

// ---------------- final projection: h3(Nx256) @ Wo(256x18) + bo ----------------
__global__ void k_out(const float* __restrict__ Wo, const float* __restrict__ bo,
                      float* __restrict__ out, int M) {
    int warp = (blockIdx.x * blockDim.x + threadIdx.x) >> 5;
    int lane = threadIdx.x & 31;
    if (warp >= M) return;
    float acc[TSTEPS];
#pragma unroll
    for (int j = 0; j < TSTEPS; j++) acc[j] = 0.f;
    const float* a = g_Z + (size_t)warp * 256;
    for (int k = lane; k < 256; k += 32) {
        float av = a[k];
        const float* wr = Wo + k * TSTEPS;
#pragma unroll
        for (int j = 0; j < TSTEPS; j++) acc[j] += av * wr[j];
    }
#pragma unroll
    for (int off = 16; off > 0; off >>= 1)
#pragma unroll
        for (int j = 0; j < TSTEPS; j++)
            acc[j] += __shfl_xor_sync(0xffffffffu, acc[j], off);
    if (lane == 0) {
        float* o = out + (size_t)warp * TSTEPS;
#pragma unroll
        for (int j = 0; j < TSTEPS; j++) o[j] = acc[j] + bo[j];
    }
}

// ---------------- launch ----------------
extern "C" void kernel_launch(void* const* d_in, const int* in_sizes, int n_in,
                              void* d_out, int out_size) {
    const float* x   = (const float*)d_in[0];
    const void*  ei  = d_in[1];
    const float* w   = (const float*)d_in[2];
    const float *Wz = (const float*)d_in[3],  *bz = (const float*)d_in[4];
    const float *Wlz= (const float*)d_in[5],  *blz= (const float*)d_in[6];
    const float *Wr = (const float*)d_in[7],  *br = (const float*)d_in[8];
    const float *Wlr= (const float*)d_in[9],  *blr= (const float*)d_in[10];
    const float *Wh = (const float*)d_in[11], *bh = (const float*)d_in[12];
    const float *Wlh= (const float*)d_in[13], *blh= (const float*)d_in[14];
    const float *att= (const float*)d_in[15];
    const float *W1 = (const float*)d_in[16], *b1 = (const float*)d_in[17];
    const float *W2 = (const float*)d_in[18], *b2 = (const float*)d_in[19];
    const float *W3 = (const float*)d_in[20], *b3 = (const float*)d_in[21];
    const float *Wo = (const float*)d_in[22], *bo = (const float*)d_in[23];
    float* out = (float*)d_out;

    const int E = in_sizes[2];
    const int N = in_sizes[0] / FT;
    const int nh = N * UNITS;

    k_init<<<(nh + 255) / 256, 256>>>((const int*)ei, N, nh);
    k_deg <<<(E + 255) / 256, 256>>>(ei, w, E);
    {
        int tot = E + N * 36;
        k_normax<<<(tot + 255) / 256, 256>>>(x, ei, w, E, N);
    }
    {
        long long tot = (long long)E * 36;
        k_axedge<<<(unsigned)((tot + 255) / 256), 256>>>(x, ei, E);
    }
    k_probs<<<1, 32>>>(att);

    const int bb = (265 * 256 + 255) / 256;
    k_buildB<<<bb, 256>>>(Wz, Wlz, bz, blz, 0);
    k_buildB<<<bb, 256>>>(Wr, Wlr, br, blr, 1);
    k_buildB<<<bb, 256>>>(Wh, Wlh, bh, blh, 2);
    k_splitW<<<(3 * 65536 + 255) / 256, 256>>>(W1, W2, W3);

    const int gbm = (N + BMt - 1) / BMt;
    for (int t = 0; t < TSTEPS; t++) {
        gemm_tc<<<dim3(4, gbm), 256>>>(nullptr, N, 512, 0, t);
        gemm_tc<<<dim3(2, gbm), 256>>>(nullptr, N, 256, 1, t);
    }

    gemm_tc<<<dim3(2, gbm), 256>>>(b1, N, 256, 2, 0);
    gemm_tc<<<dim3(2, gbm), 256>>>(b2, N, 256, 3, 0);
    gemm_tc<<<dim3(2, gbm), 256>>>(b3, N, 256, 4, 0);

    k_out<<<(N * 32 + 255) / 256, 256>>>(Wo, bo, out, N);
}

// round 7
// speedup vs baseline: 1.4438x; 1.4438x over previous
#include <cuda_runtime.h>
#include <cuda_bf16.h>
#include <math.h>
#include <stdint.h>

// ---------------- problem constants ----------------
#define NODES   100000
#define EDGESMX 1600000
#define UNITS   256
#define TSTEPS  18
#define FIN     8
#define FT      144            // FIN * TSTEPS
#define NH      (NODES*UNITS)
#define K2ZR    136            // 272 K rows / 2 (bf16 pairs), gates
#define K2M     128            // 256 K rows / 2, MLP

// ---------------- device scratch ----------------
__device__ __align__(16) float g_deg [NODES];
__device__ __align__(16) float g_norm[EDGESMX];
__device__ __align__(16) float g_AX[(size_t)NODES * FT];
__device__ __align__(16) float g_H [(size_t)NH];
__device__ __align__(16) float g_Z [(size_t)NH];
__device__ __align__(16) float g_HR[(size_t)NH];
__device__ __align__(16) float g_acc[(size_t)NH];
// bf16x3-split weights, packed as bf16 pairs over consecutive k
__device__ __align__(16) uint32_t g_Bzr_hi[K2ZR * 512];
__device__ __align__(16) uint32_t g_Bzr_lo[K2ZR * 512];
__device__ __align__(16) uint32_t g_Bh_hi [K2ZR * 256];
__device__ __align__(16) uint32_t g_Bh_lo [K2ZR * 256];
__device__ __align__(16) uint32_t g_Bm_hi [3 * K2M * 256];
__device__ __align__(16) uint32_t g_Bm_lo [3 * K2M * 256];
__device__ __align__(16) float g_czr[512];
__device__ __align__(16) float g_ch [256];
__device__ __align__(16) float g_probs[TSTEPS];
__device__ int g_is64;

// ---------------- bf16 helpers ----------------
__device__ __forceinline__ uint32_t pack_bf16(float x, float y) {
    __nv_bfloat162 p = __floats2bfloat162_rn(x, y);
    return *reinterpret_cast<uint32_t*>(&p);
}
__device__ __forceinline__ void split_pack(float v0, float v1, uint32_t& hi, uint32_t& lo) {
    __nv_bfloat16 h0 = __float2bfloat16_rn(v0);
    __nv_bfloat16 h1 = __float2bfloat16_rn(v1);
    float r0 = v0 - __bfloat162float(h0);
    float r1 = v1 - __bfloat162float(h1);
    __nv_bfloat162 ph; ph.x = h0; ph.y = h1;
    hi = *reinterpret_cast<uint32_t*>(&ph);
    lo = pack_bf16(r0, r1);
}

__device__ __forceinline__ int edge_at(const void* ei, long long i) {
    if (g_is64) return (int)((const long long*)ei)[i];
    return ((const int*)ei)[i];
}

// ---------------- setup kernels ----------------
__global__ void k_init(const int* __restrict__ ei32, int n, int nh) {
    int i = blockIdx.x * blockDim.x + threadIdx.x;
    if (i == 0) {
        int is64 = 1;
        for (int q = 1; q < 64; q += 2)
            if (ei32[q] != 0) { is64 = 0; break; }
        g_is64 = is64;
    }
    if (i < nh) { g_H[i] = 0.f; g_acc[i] = 0.f; }
    if (i < n)  g_deg[i] = 1.0f;
}

__global__ void k_deg(const void* __restrict__ ei, const float* __restrict__ w, int E) {
    int e = blockIdx.x * blockDim.x + threadIdx.x;
    if (e < E) atomicAdd(&g_deg[edge_at(ei, (long long)E + e)], w[e]);
}

__global__ void k_normax(const float* __restrict__ x, const void* __restrict__ ei,
                         const float* __restrict__ w, int E, int n) {
    int idx = blockIdx.x * blockDim.x + threadIdx.x;
    if (idx < E) {
        int s = edge_at(ei, idx);
        int d = edge_at(ei, (long long)E + idx);
        g_norm[idx] = rsqrtf(g_deg[s]) * w[idx] * rsqrtf(g_deg[d]);
    } else {
        int j2 = idx - E;
        if (j2 >= n * 36) return;
        int node = j2 / 36, j = j2 % 36;
        float r = rsqrtf(g_deg[node]); float c = r * r;
        const float4 xv = *reinterpret_cast<const float4*>(&x[(size_t)node * FT + j * 4]);
        float4 o = make_float4(c*xv.x, c*xv.y, c*xv.z, c*xv.w);
        *reinterpret_cast<float4*>(&g_AX[(size_t)node * FT + j * 4]) = o;
    }
}

__global__ void k_axedge(const float* __restrict__ x, const void* __restrict__ ei, int E) {
    long long idx = (long long)blockIdx.x * blockDim.x + threadIdx.x;
    if (idx >= (long long)E * 36) return;
    int e = (int)(idx / 36), j = (int)(idx % 36);
    int s = edge_at(ei, e);
    int d = edge_at(ei, (long long)E + e);
    float c = g_norm[e];
    const float4 xv = *reinterpret_cast<const float4*>(&x[(size_t)s * FT + j * 4]);
    float* p = &g_AX[(size_t)d * FT + j * 4];
    asm volatile("red.global.add.v4.f32 [%0], {%1,%2,%3,%4};"
                 :: "l"(__cvta_generic_to_global(p)),
                    "f"(c*xv.x), "f"(c*xv.y), "f"(c*xv.z), "f"(c*xv.w)
                 : "memory");
}

__global__ void k_probs(const float* __restrict__ att) {
    if (threadIdx.x == 0) {
        float mx = -1e30f;
        for (int i = 0; i < TSTEPS; i++) mx = fmaxf(mx, att[i]);
        float s = 0.f, e[TSTEPS];
        for (int i = 0; i < TSTEPS; i++) { e[i] = expf(att[i] - mx); s += e[i]; }
        float inv = 1.f / s;
        for (int i = 0; i < TSTEPS; i++) g_probs[i] = e[i] * inv;
    }
}

// Fold gconv into gate linear; write bf16 hi/lo pair-packed. K rows: 256 H + 8 AX + 8 zero = 272.
__global__ void k_buildB(const float* __restrict__ Wg, const float* __restrict__ Wl,
                         const float* __restrict__ bg, const float* __restrict__ bl,
                         int which) {
    uint32_t* Bhi = (which == 2) ? g_Bh_hi : g_Bzr_hi;
    uint32_t* Blo = (which == 2) ? g_Bh_lo : g_Bzr_lo;
    float* cout = (which == 2) ? g_ch : g_czr;
    const int ldb    = (which == 2) ? 256 : 512;
    const int coloff = (which == 1) ? 256 : 0;

    int idx = blockIdx.x * blockDim.x + threadIdx.x;
    if (idx >= (K2ZR + 1) * 256) return;
    int k2 = idx >> 8, n = idx & 255;
    if (k2 == K2ZR) {   // bias row
        float s = bl[n];
        for (int i = 0; i < 256; i++) s += bg[i] * Wl[(size_t)i * 256 + n];
        cout[coloff + n] = s;
        return;
    }
    float v[2];
#pragma unroll
    for (int h = 0; h < 2; h++) {
        int k = k2 * 2 + h;
        if (k < 256) {
            v[h] = Wl[(size_t)(256 + k) * 256 + n];
        } else if (k < 264) {
            int f = k - 256;
            float s = 0.f;
            for (int i = 0; i < 256; i++) s += Wg[f * 256 + i] * Wl[(size_t)i * 256 + n];
            v[h] = s;
        } else {
            v[h] = 0.f;
        }
    }
    uint32_t hi, lo; split_pack(v[0], v[1], hi, lo);
    Bhi[(size_t)k2 * ldb + coloff + n] = hi;
    Blo[(size_t)k2 * ldb + coloff + n] = lo;
}

// Split MLP weights (3 x 256x256) into bf16 hi/lo pair-packed
__global__ void k_splitW(const float* __restrict__ W1, const float* __restrict__ W2,
                         const float* __restrict__ W3) {
    int idx = blockIdx.x * blockDim.x + threadIdx.x;
    if (idx >= 3 * K2M * 256) return;
    int which = idx / (K2M * 256), r = idx % (K2M * 256);
    int k2 = r >> 8, n = r & 255;
    const float* W = (which == 0) ? W1 : (which == 1) ? W2 : W3;
    uint32_t hi, lo;
    split_pack(W[(size_t)(2 * k2) * 256 + n], W[(size_t)(2 * k2 + 1) * 256 + n], hi, lo);
    g_Bm_hi[idx] = hi;
    g_Bm_lo[idx] = lo;
}

// ---------------- 3xBF16 tensor-core GEMM (m16n8k16), double-buffered, fused epilogues ----------------
// modes:
//  0: [H | AX_t] @ Bzr + czr -> sigmoid; n<256: g_Z, n>=256: g_HR = s*H
//  1: [HR| AX_t] @ Bh  + ch  -> tanh; GRU update g_H, g_acc += p_t*Hn
//  2: relu(g_acc) @ Bm0 + b -> relu -> g_Z
//  3: g_Z         @ Bm1 + b -> relu -> g_HR
//  4: g_HR        @ Bm2 + b -> relu -> g_Z
#define BMt 128
#define BNt 128
#define TLD 132   // padded leading dim; rows are k2 (pairs)

__device__ __forceinline__ void mma_bf16(float c[4], const uint32_t a[4], const uint32_t b[2]) {
    asm volatile(
        "mma.sync.aligned.m16n8k16.row.col.f32.bf16.bf16.f32 "
        "{%0,%1,%2,%3}, {%4,%5,%6,%7}, {%8,%9}, {%0,%1,%2,%3};\n"
        : "+f"(c[0]), "+f"(c[1]), "+f"(c[2]), "+f"(c[3])
        : "r"(a[0]), "r"(a[1]), "r"(a[2]), "r"(a[3]), "r"(b[0]), "r"(b[1]));
}

__global__ __launch_bounds__(256, 2)
void gemm_tc(const float* __restrict__ biasp, int M, int N, int mode, int t) {
    const float* A = (mode == 0) ? g_H : (mode == 1) ? g_HR
                   : (mode == 2) ? g_acc : (mode == 3) ? g_Z : g_HR;
    const uint32_t* Bhi; const uint32_t* Blo;
    if      (mode == 0) { Bhi = g_Bzr_hi; Blo = g_Bzr_lo; }
    else if (mode == 1) { Bhi = g_Bh_hi;  Blo = g_Bh_lo;  }
    else { Bhi = g_Bm_hi + (size_t)(mode - 2) * K2M * 256;
           Blo = g_Bm_lo + (size_t)(mode - 2) * K2M * 256; }
    const float* bias = (mode == 0) ? g_czr : (mode == 1) ? g_ch : biasp;
    const bool useAX = (mode <= 1);
    const bool reluA = (mode == 2);

    // tiles: 8 k2-rows (= K 16) x 128
    __shared__ uint32_t AsH[2][8][TLD];
    __shared__ uint32_t AsL[2][8][TLD];
    __shared__ uint32_t BsH[2][8][TLD];
    __shared__ uint32_t BsL[2][8][TLD];

    const int tid = threadIdx.x, lane = tid & 31, wid = tid >> 5;
    const int wm = (wid & 1) * 64;
    const int wn = (wid >> 1) * 32;
    const int g = lane >> 2, tg = lane & 3;
    const int bn = blockIdx.x * BNt, bm = blockIdx.y * BMt;   // x = n-tile (L2 reuse of A)

    const int aRow = tid >> 1, aHalf = tid & 1;      // A: row m = aRow, k2 cols aHalf*4..+3
    const int bRow = tid >> 5, bCol = lane * 4;      // B: k2 row, 4 n per thread
    const int m = bm + aRow;

    float c[4][4][4];
#pragma unroll
    for (int i = 0; i < 4; i++)
#pragma unroll
        for (int j = 0; j < 4; j++)
#pragma unroll
            for (int q = 0; q < 4; q++) c[i][j][q] = 0.f;

    const int nT = useAX ? 17 : 16;

    auto loadA = [&](int kt, float v[8]) {
#pragma unroll
        for (int i = 0; i < 8; i++) v[i] = 0.f;
        if (kt < 16) {
            if (m < M) {
                const float* ap = &A[(size_t)m * 256 + kt * 16 + aHalf * 8];
                float4 u0 = *reinterpret_cast<const float4*>(ap);
                float4 u1 = *reinterpret_cast<const float4*>(ap + 4);
                v[0]=u0.x; v[1]=u0.y; v[2]=u0.z; v[3]=u0.w;
                v[4]=u1.x; v[5]=u1.y; v[6]=u1.z; v[7]=u1.w;
                if (reluA) {
#pragma unroll
                    for (int i = 0; i < 8; i++) v[i] = fmaxf(v[i], 0.f);
                }
            }
        } else {
            // AX tile: k 0..7 = features (first half threads), k 8..15 zero
            if (aHalf == 0 && m < M) {
                const float* ax = &g_AX[(size_t)m * FT + t];
#pragma unroll
                for (int i = 0; i < 8; i++) v[i] = ax[i * TSTEPS];
            }
        }
    };
    auto loadB = [&](int kt, uint4& vh, uint4& vl) {
        size_t off = (size_t)(kt * 8 + bRow) * N + bn + bCol;
        vh = *reinterpret_cast<const uint4*>(&Bhi[off]);
        vl = *reinterpret_cast<const uint4*>(&Blo[off]);
    };
    auto storeTile = [&](int buf, const float v[8], const uint4& vh, const uint4& vl) {
#pragma unroll
        for (int i = 0; i < 4; i++) {
            uint32_t hi, lo;
            split_pack(v[2*i], v[2*i+1], hi, lo);
            AsH[buf][aHalf * 4 + i][aRow] = hi;
            AsL[buf][aHalf * 4 + i][aRow] = lo;
        }
        BsH[buf][bRow][bCol + 0] = vh.x; BsH[buf][bRow][bCol + 1] = vh.y;
        BsH[buf][bRow][bCol + 2] = vh.z; BsH[buf][bRow][bCol + 3] = vh.w;
        BsL[buf][bRow][bCol + 0] = vl.x; BsL[buf][bRow][bCol + 1] = vl.y;
        BsL[buf][bRow][bCol + 2] = vl.z; BsL[buf][bRow][bCol + 3] = vl.w;
    };

    // prologue
    {
        float v[8]; uint4 vh, vl;
        loadA(0, v); loadB(0, vh, vl);
        storeTile(0, v, vh, vl);
    }
    __syncthreads();

    for (int kt = 0; kt < nT; kt++) {
        const int cur = kt & 1, nxt = cur ^ 1;
        float v[8]; uint4 vh, vl;
        const bool pf = (kt + 1 < nT);
        if (pf) { loadA(kt + 1, v); loadB(kt + 1, vh, vl); }

        uint32_t bh[4][2], bl[4][2];
#pragma unroll
        for (int ni = 0; ni < 4; ni++) {
            int n0 = wn + ni * 8;
            bh[ni][0] = BsH[cur][tg][n0 + g];
            bh[ni][1] = BsH[cur][tg + 4][n0 + g];
            bl[ni][0] = BsL[cur][tg][n0 + g];
            bl[ni][1] = BsL[cur][tg + 4][n0 + g];
        }
#pragma unroll
        for (int mi = 0; mi < 4; mi++) {
            int m0 = wm + mi * 16;
            uint32_t ah[4], al[4];
            ah[0] = AsH[cur][tg][m0 + g];     ah[1] = AsH[cur][tg][m0 + g + 8];
            ah[2] = AsH[cur][tg + 4][m0 + g]; ah[3] = AsH[cur][tg + 4][m0 + g + 8];
            al[0] = AsL[cur][tg][m0 + g];     al[1] = AsL[cur][tg][m0 + g + 8];
            al[2] = AsL[cur][tg + 4][m0 + g]; al[3] = AsL[cur][tg + 4][m0 + g + 8];
#pragma unroll
            for (int ni = 0; ni < 4; ni++) {
                mma_bf16(c[mi][ni], ah, bl[ni]);
                mma_bf16(c[mi][ni], al, bh[ni]);
                mma_bf16(c[mi][ni], ah, bh[ni]);
            }
        }

        if (pf) storeTile(nxt, v, vh, vl);
        __syncthreads();
    }

    // ---- fused epilogue ----
    const float pt = (mode == 1) ? g_probs[t] : 0.f;
#pragma unroll
    for (int mi = 0; mi < 4; mi++) {
        int r0 = bm + wm + mi * 16 + g;
#pragma unroll
        for (int half = 0; half < 2; half++) {
            int r = r0 + half * 8;
            if (r >= M) continue;
            size_t base = (size_t)r * 256;
#pragma unroll
            for (int ni = 0; ni < 4; ni++) {
                int n = bn + wn + ni * 8 + tg * 2;
                float v0 = c[mi][ni][half * 2 + 0] + bias[n];
                float v1 = c[mi][ni][half * 2 + 1] + bias[n + 1];
                if (mode == 0) {
                    float s0 = 1.f / (1.f + expf(-v0));
                    float s1 = 1.f / (1.f + expf(-v1));
                    if (n < 256) {
                        g_Z[base + n] = s0; g_Z[base + n + 1] = s1;
                    } else {
                        int n2 = n - 256;
                        g_HR[base + n2]     = s0 * g_H[base + n2];
                        g_HR[base + n2 + 1] = s1 * g_H[base + n2 + 1];
                    }
                } else if (mode == 1) {
                    float h0 = tanhf(v0), h1 = tanhf(v1);
                    float z0 = g_Z[base + n], z1 = g_Z[base + n + 1];
                    float o0 = g_H[base + n], o1 = g_H[base + n + 1];
                    float hn0 = z0 * o0 + (1.f - z0) * h0;
                    float hn1 = z1 * o1 + (1.f - z1) * h1;
                    g_H[base + n] = hn0; g_H[base + n + 1] = hn1;
                    g_acc[base + n]     += pt * hn0;
                    g_acc[base + n + 1] += pt * hn1;
                } else {
                    float r0v = fmaxf(v0, 0.f), r1v = fmaxf(v1, 0.f);
                    if (mode == 3) { g_HR[base + n] = r0v; g_HR[base + n + 1] = r1v; }
                    else           { g_Z [base + n] = r0v; g_Z [base + n + 1] = r1v; }
                }
            }
        }
    }
}

// ---------------- final projection: h3(Nx256) @ Wo(256x18) + bo ----------------
__global__ void k_out(const float* __restrict__ Wo, const float* __restrict__ bo,
                      float* __restrict__ out, int M) {
    int warp = (blockIdx.x * blockDim.x + threadIdx.x) >> 5;
    int lane = threadIdx.x & 31;
    if (warp >= M) return;
    float acc[TSTEPS];
#pragma unroll
    for (int j = 0; j < TSTEPS; j++) acc[j] = 0.f;
    const float* a = g_Z + (size_t)warp * 256;
    for (int k = lane; k < 256; k += 32) {
        float av = a[k];
        const float* wr = Wo + k * TSTEPS;
#pragma unroll
        for (int j = 0; j < TSTEPS; j++) acc[j] += av * wr[j];
    }
#pragma unroll
    for (int off = 16; off > 0; off >>= 1)
#pragma unroll
        for (int j = 0; j < TSTEPS; j++)
            acc[j] += __shfl_xor_sync(0xffffffffu, acc[j], off);
    if (lane == 0) {
        float* o = out + (size_t)warp * TSTEPS;
#pragma unroll
        for (int j = 0; j < TSTEPS; j++) o[j] = acc[j] + bo[j];
    }
}

// ---------------- launch ----------------
extern "C" void kernel_launch(void* const* d_in, const int* in_sizes, int n_in,
                              void* d_out, int out_size) {
    const float* x   = (const float*)d_in[0];
    const void*  ei  = d_in[1];
    const float* w   = (const float*)d_in[2];
    const float *Wz = (const float*)d_in[3],  *bz = (const float*)d_in[4];
    const float *Wlz= (const float*)d_in[5],  *blz= (const float*)d_in[6];
    const float *Wr = (const float*)d_in[7],  *br = (const float*)d_in[8];
    const float *Wlr= (const float*)d_in[9],  *blr= (const float*)d_in[10];
    const float *Wh = (const float*)d_in[11], *bh = (const float*)d_in[12];
    const float *Wlh= (const float*)d_in[13], *blh= (const float*)d_in[14];
    const float *att= (const float*)d_in[15];
    const float *W1 = (const float*)d_in[16], *b1 = (const float*)d_in[17];
    const float *W2 = (const float*)d_in[18], *b2 = (const float*)d_in[19];
    const float *W3 = (const float*)d_in[20], *b3 = (const float*)d_in[21];
    const float *Wo = (const float*)d_in[22], *bo = (const float*)d_in[23];
    float* out = (float*)d_out;

    const int E = in_sizes[2];
    const int N = in_sizes[0] / FT;
    const int nh = N * UNITS;

    k_init<<<(nh + 255) / 256, 256>>>((const int*)ei, N, nh);
    k_deg <<<(E + 255) / 256, 256>>>(ei, w, E);
    {
        int tot = E + N * 36;
        k_normax<<<(tot + 255) / 256, 256>>>(x, ei, w, E, N);
    }
    {
        long long tot = (long long)E * 36;
        k_axedge<<<(unsigned)((tot + 255) / 256), 256>>>(x, ei, E);
    }
    k_probs<<<1, 32>>>(att);

    const int bb = ((K2ZR + 1) * 256 + 255) / 256;
    k_buildB<<<bb, 256>>>(Wz, Wlz, bz, blz, 0);
    k_buildB<<<bb, 256>>>(Wr, Wlr, br, blr, 1);
    k_buildB<<<bb, 256>>>(Wh, Wlh, bh, blh, 2);
    k_splitW<<<(3 * K2M * 256 + 255) / 256, 256>>>(W1, W2, W3);

    const int gbm = (N + BMt - 1) / BMt;
    for (int t = 0; t < TSTEPS; t++) {
        gemm_tc<<<dim3(4, gbm), 256>>>(nullptr, N, 512, 0, t);
        gemm_tc<<<dim3(2, gbm), 256>>>(nullptr, N, 256, 1, t);
    }

    gemm_tc<<<dim3(2, gbm), 256>>>(b1, N, 256, 2, 0);
    gemm_tc<<<dim3(2, gbm), 256>>>(b2, N, 256, 3, 0);
    gemm_tc<<<dim3(2, gbm), 256>>>(b3, N, 256, 4, 0);

    k_out<<<(N * 32 + 255) / 256, 256>>>(Wo, bo, out, N);
}

// round 9
// speedup vs baseline: 1.5811x; 1.0951x over previous
#include <cuda_runtime.h>
#include <cuda_bf16.h>
#include <math.h>
#include <stdint.h>

// ---------------- problem constants ----------------
#define NODES   100000
#define EDGESMX 1600000
#define TSTEPS  18
#define FIN     8
#define FT      144
#define NH      (NODES*256)

// ---------------- device scratch ----------------
__device__ __align__(16) float g_deg [NODES];
__device__ __align__(16) float g_norm[EDGESMX];
__device__ __align__(16) float g_AX[(size_t)NODES * FT];
__device__ __align__(16) float g_H  [(size_t)NH];
__device__ __align__(16) float g_Z  [(size_t)NH];
__device__ __align__(16) float g_acc[(size_t)NH];
// transposed pre-split activations: [k2 (bf16 pair)][node]
__device__ __align__(16) uint32_t g_Hhi [(size_t)128 * NODES];
__device__ __align__(16) uint32_t g_Hlo [(size_t)128 * NODES];
__device__ __align__(16) uint32_t g_HRhi[(size_t)128 * NODES];
__device__ __align__(16) uint32_t g_HRlo[(size_t)128 * NODES];
__device__ __align__(16) uint32_t g_M0hi[(size_t)128 * NODES];
__device__ __align__(16) uint32_t g_M0lo[(size_t)128 * NODES];
__device__ __align__(16) uint32_t g_M1hi[(size_t)128 * NODES];
__device__ __align__(16) uint32_t g_M1lo[(size_t)128 * NODES];
// AX split: [(k2 0..3)*TSTEPS + t][node]
__device__ __align__(16) uint32_t g_AXhi[(size_t)4 * TSTEPS * NODES];
__device__ __align__(16) uint32_t g_AXlo[(size_t)4 * TSTEPS * NODES];
// k2-major split weights: gates 144 k2-rows (256 H + 8 AX + pad), MLP 128 rows
__device__ __align__(16) uint32_t g_Bzrh[144 * 512];
__device__ __align__(16) uint32_t g_Bzrl[144 * 512];
__device__ __align__(16) uint32_t g_Bhh [144 * 256];
__device__ __align__(16) uint32_t g_Bhl [144 * 256];
__device__ __align__(16) uint32_t g_Bmh [3 * 128 * 256];
__device__ __align__(16) uint32_t g_Bml [3 * 128 * 256];
__device__ __align__(16) float g_czr[512];
__device__ __align__(16) float g_ch [256];
__device__ __align__(16) float g_probs[TSTEPS];
__device__ int g_is64;

// ---------------- helpers ----------------
__device__ __forceinline__ void split_pack(float v0, float v1, uint32_t& hi, uint32_t& lo) {
    __nv_bfloat16 h0 = __float2bfloat16_rn(v0);
    __nv_bfloat16 h1 = __float2bfloat16_rn(v1);
    __nv_bfloat162 ph; ph.x = h0; ph.y = h1;
    hi = *reinterpret_cast<uint32_t*>(&ph);
    __nv_bfloat162 pl = __floats2bfloat162_rn(v0 - __bfloat162float(h0),
                                              v1 - __bfloat162float(h1));
    lo = *reinterpret_cast<uint32_t*>(&pl);
}
__device__ __forceinline__ int edge_at(const void* ei, long long i) {
    if (g_is64) return (int)((const long long*)ei)[i];
    return ((const int*)ei)[i];
}
__device__ __forceinline__ uint32_t smem_u32(const void* p) {
    uint32_t a;
    asm("{ .reg .u64 t; cvta.to.shared.u64 t, %1; cvt.u32.u64 %0, t; }" : "=r"(a) : "l"(p));
    return a;
}
__device__ __forceinline__ void cp16(uint32_t dst, const void* src) {
    asm volatile("cp.async.cg.shared.global [%0], [%1], 16;" :: "r"(dst), "l"(src));
}
__device__ __forceinline__ void z16(uint32_t dst) {
    asm volatile("st.shared.v4.u32 [%0], {%1,%1,%1,%1};" :: "r"(dst), "r"(0u));
}
#define CP_COMMIT() asm volatile("cp.async.commit_group;" ::: "memory")
#define CP_WAIT0()  asm volatile("cp.async.wait_group 0;" ::: "memory")
#define CP_WAIT1()  asm volatile("cp.async.wait_group 1;" ::: "memory")

__device__ __forceinline__ void mma_bf16(float c[4], const uint32_t a[4], const uint32_t b[2]) {
    asm volatile(
        "mma.sync.aligned.m16n8k16.row.col.f32.bf16.bf16.f32 "
        "{%0,%1,%2,%3}, {%4,%5,%6,%7}, {%8,%9}, {%0,%1,%2,%3};\n"
        : "+f"(c[0]), "+f"(c[1]), "+f"(c[2]), "+f"(c[3])
        : "r"(a[0]), "r"(a[1]), "r"(a[2]), "r"(a[3]), "r"(b[0]), "r"(b[1]));
}

// ---------------- setup kernels ----------------
__global__ void k_init(const int* __restrict__ ei32, int n, int nh) {
    int i = blockIdx.x * blockDim.x + threadIdx.x;
    if (i == 0) {
        int is64 = 1;
        for (int q = 1; q < 64; q += 2)
            if (ei32[q] != 0) { is64 = 0; break; }
        g_is64 = is64;
    }
    if (i < nh) { g_H[i] = 0.f; g_acc[i] = 0.f; }
    if (i < nh / 2) { g_Hhi[i] = 0u; g_Hlo[i] = 0u; }
    if (i < n) g_deg[i] = 1.0f;
}

__global__ void k_deg(const void* __restrict__ ei, const float* __restrict__ w, int E) {
    int e = blockIdx.x * blockDim.x + threadIdx.x;
    if (e < E) atomicAdd(&g_deg[edge_at(ei, (long long)E + e)], w[e]);
}

__global__ void k_normax(const float* __restrict__ x, const void* __restrict__ ei,
                         const float* __restrict__ w, int E, int n) {
    int idx = blockIdx.x * blockDim.x + threadIdx.x;
    if (idx < E) {
        int s = edge_at(ei, idx);
        int d = edge_at(ei, (long long)E + idx);
        g_norm[idx] = rsqrtf(g_deg[s]) * w[idx] * rsqrtf(g_deg[d]);
    } else {
        int j2 = idx - E;
        if (j2 >= n * 36) return;
        int node = j2 / 36, j = j2 % 36;
        float r = rsqrtf(g_deg[node]); float c = r * r;
        const float4 xv = *reinterpret_cast<const float4*>(&x[(size_t)node * FT + j * 4]);
        float4 o = make_float4(c*xv.x, c*xv.y, c*xv.z, c*xv.w);
        *reinterpret_cast<float4*>(&g_AX[(size_t)node * FT + j * 4]) = o;
    }
}

__global__ void k_axedge(const float* __restrict__ x, const void* __restrict__ ei, int E) {
    long long idx = (long long)blockIdx.x * blockDim.x + threadIdx.x;
    if (idx >= (long long)E * 36) return;
    int e = (int)(idx / 36), j = (int)(idx % 36);
    int s = edge_at(ei, e);
    int d = edge_at(ei, (long long)E + e);
    float c = g_norm[e];
    const float4 xv = *reinterpret_cast<const float4*>(&x[(size_t)s * FT + j * 4]);
    float* p = &g_AX[(size_t)d * FT + j * 4];
    asm volatile("red.global.add.v4.f32 [%0], {%1,%2,%3,%4};"
                 :: "l"(__cvta_generic_to_global(p)),
                    "f"(c*xv.x), "f"(c*xv.y), "f"(c*xv.z), "f"(c*xv.w)
                 : "memory");
}

// AX split into transposed [(k2*TSTEPS + t)][node]; idx = m*TSTEPS + t (row reuse in L1)
__global__ void k_axsplit(int n) {
    int idx = blockIdx.x * blockDim.x + threadIdx.x;
    if (idx >= n * TSTEPS) return;
    int m = idx / TSTEPS, t = idx % TSTEPS;
    const float* ax = &g_AX[(size_t)m * FT + t];
#pragma unroll
    for (int i = 0; i < 4; i++) {
        uint32_t hi, lo;
        split_pack(ax[(2*i) * TSTEPS], ax[(2*i+1) * TSTEPS], hi, lo);
        size_t o = (size_t)(i * TSTEPS + t) * NODES + m;
        g_AXhi[o] = hi; g_AXlo[o] = lo;
    }
}

__global__ void k_probs(const float* __restrict__ att) {
    if (threadIdx.x == 0) {
        float mx = -1e30f;
        for (int i = 0; i < TSTEPS; i++) mx = fmaxf(mx, att[i]);
        float s = 0.f, e[TSTEPS];
        for (int i = 0; i < TSTEPS; i++) { e[i] = expf(att[i] - mx); s += e[i]; }
        float inv = 1.f / s;
        for (int i = 0; i < TSTEPS; i++) g_probs[i] = e[i] * inv;
    }
}

// Gate weights, k2-major (row k2, cols n), hi/lo split; rows 128..131 = folded AX, 132..143 = 0
__global__ void k_buildB(const float* __restrict__ Wg, const float* __restrict__ Wl,
                         const float* __restrict__ bg, const float* __restrict__ bl,
                         int which) {
    int idx = blockIdx.x * blockDim.x + threadIdx.x;
    if (idx >= 145 * 256) return;
    int k2 = idx >> 8, n = idx & 255;
    const int coloff = (which == 1) ? 256 : 0;
    if (k2 == 144) {  // bias
        float s = bl[n];
        for (int i = 0; i < 256; i++) s += bg[i] * Wl[(size_t)i * 256 + n];
        if (which == 2) g_ch[n] = s; else g_czr[coloff + n] = s;
        return;
    }
    float v[2];
#pragma unroll
    for (int h = 0; h < 2; h++) {
        int k = k2 * 2 + h;
        if (k < 256) v[h] = Wl[(size_t)(256 + k) * 256 + n];
        else if (k < 264) {
            int f = k - 256; float s = 0.f;
            for (int i = 0; i < 256; i++) s += Wg[f * 256 + i] * Wl[(size_t)i * 256 + n];
            v[h] = s;
        } else v[h] = 0.f;
    }
    uint32_t hi, lo; split_pack(v[0], v[1], hi, lo);
    if (which == 2) { g_Bhh[k2 * 256 + n] = hi; g_Bhl[k2 * 256 + n] = lo; }
    else { g_Bzrh[k2 * 512 + coloff + n] = hi; g_Bzrl[k2 * 512 + coloff + n] = lo; }
}

__global__ void k_splitW(const float* __restrict__ W1, const float* __restrict__ W2,
                         const float* __restrict__ W3) {
    int idx = blockIdx.x * blockDim.x + threadIdx.x;
    if (idx >= 3 * 128 * 256) return;
    int which = idx / 32768, r = idx % 32768;
    int k2 = r >> 8, n = r & 255;
    const float* W = (which == 0) ? W1 : (which == 1) ? W2 : W3;
    uint32_t hi, lo;
    split_pack(W[(size_t)(2*k2) * 256 + n], W[(size_t)(2*k2+1) * 256 + n], hi, lo);
    g_Bmh[idx] = hi; g_Bml[idx] = lo;
}

// ---------------- 3xBF16 legacy-mma GEMM, cp.async double-buffered, K=32/iter ----------------
// modes: 0 gates Z|R (N=512, ny 0..3), 1 candidate (N=256), 2/3/4 MLP
#define TLD 132
#define STG 8448   // u32 per stage: AH 2112 | AL 2112 | BH 2112 | BL 2112
#define SMEM_BYTES (2 * STG * 4)

__global__ __launch_bounds__(256, 2)
void gemmx(const float* __restrict__ biasp, int M, int mode, int t, int last) {
    extern __shared__ uint32_t smdyn[];
    const uint32_t sbase = smem_u32(smdyn);
    const int tid = threadIdx.x, lane = tid & 31, wid = tid >> 5;
    const int g = lane >> 2, tg = lane & 3;
    const int wm = (wid & 1) * 64, wn = (wid >> 1) * 32;
    const int ny = blockIdx.x, bm = blockIdx.y * 128;

    const uint32_t *Ahi, *Alo, *Bhi, *Blo; int ldn, nC;
    if (mode == 0)      { Ahi=g_Hhi;  Alo=g_Hlo;  Bhi=g_Bzrh; Blo=g_Bzrl; ldn=512; nC=9; }
    else if (mode == 1) { Ahi=g_HRhi; Alo=g_HRlo; Bhi=g_Bhh;  Blo=g_Bhl;  ldn=256; nC=9; }
    else if (mode == 2) { Ahi=g_M0hi; Alo=g_M0lo; Bhi=g_Bmh;        Blo=g_Bml;        ldn=256; nC=8; }
    else if (mode == 3) { Ahi=g_M1hi; Alo=g_M1lo; Bhi=g_Bmh+32768;  Blo=g_Bml+32768;  ldn=256; nC=8; }
    else                { Ahi=g_M0hi; Alo=g_M0lo; Bhi=g_Bmh+65536;  Blo=g_Bml+65536;  ldn=256; nC=8; }
    const float* bias = (mode == 0) ? g_czr : (mode == 1) ? g_ch : biasp;

    float c[4][4][4];
#pragma unroll
    for (int i = 0; i < 4; i++)
#pragma unroll
        for (int j = 0; j < 4; j++)
#pragma unroll
            for (int q = 0; q < 4; q++) c[i][j][q] = 0.f;

    auto stage = [&](int ck, int buf) {
        const uint32_t aH = buf * STG, aL = aH + 2112, bH = aH + 4224, bL = aH + 6336;
        const bool axc = (mode <= 1) && (ck == 8);
#pragma unroll
        for (int s2 = 0; s2 < 2; s2++) {
            int s = tid + s2 * 256;
            int kr = s >> 5, mo = (s & 31) * 4;
            int m = bm + mo;
            uint32_t dH = sbase + (aH + kr * TLD + mo) * 4;
            uint32_t dL = sbase + (aL + kr * TLD + mo) * 4;
            if (axc) {
                if (kr < 4 && m < M) {
                    size_t so = (size_t)(kr * TSTEPS + t) * NODES + m;
                    cp16(dH, g_AXhi + so); cp16(dL, g_AXlo + so);
                } else { z16(dH); z16(dL); }
            } else if (m < M) {
                size_t so = (size_t)(ck * 16 + kr) * NODES + m;
                cp16(dH, Ahi + so); cp16(dL, Alo + so);
            } else { z16(dH); z16(dL); }
        }
#pragma unroll
        for (int s2 = 0; s2 < 2; s2++) {
            int s = tid + s2 * 256;
            int kr = s >> 5, no = (s & 31) * 4;
            size_t so = (size_t)(ck * 16 + kr) * ldn + ny * 128 + no;
            cp16(sbase + (bH + kr * TLD + no) * 4, Bhi + so);
            cp16(sbase + (bL + kr * TLD + no) * 4, Blo + so);
        }
    };

    stage(0, 0); CP_COMMIT();
    for (int ck = 0; ck < nC; ck++) {
        const int buf = ck & 1;
        if (ck + 1 < nC) { stage(ck + 1, buf ^ 1); CP_COMMIT(); CP_WAIT1(); }
        else CP_WAIT0();
        __syncthreads();

        const uint32_t aH = buf * STG, aL = aH + 2112, bH = aH + 4224, bL = aH + 6336;
#pragma unroll
        for (int ks = 0; ks < 2; ks++) {
            const int rb = ks * 8;
            uint32_t bh[4][2], bl[4][2];
#pragma unroll
            for (int ni = 0; ni < 4; ni++) {
                int n0 = wn + ni * 8 + g;
                bh[ni][0] = smdyn[bH + (rb + tg) * TLD + n0];
                bh[ni][1] = smdyn[bH + (rb + tg + 4) * TLD + n0];
                bl[ni][0] = smdyn[bL + (rb + tg) * TLD + n0];
                bl[ni][1] = smdyn[bL + (rb + tg + 4) * TLD + n0];
            }
#pragma unroll
            for (int mi = 0; mi < 4; mi++) {
                int m0 = wm + mi * 16 + g;
                uint32_t ah[4], al[4];
                ah[0] = smdyn[aH + (rb + tg) * TLD + m0];
                ah[1] = smdyn[aH + (rb + tg) * TLD + m0 + 8];
                ah[2] = smdyn[aH + (rb + tg + 4) * TLD + m0];
                ah[3] = smdyn[aH + (rb + tg + 4) * TLD + m0 + 8];
                al[0] = smdyn[aL + (rb + tg) * TLD + m0];
                al[1] = smdyn[aL + (rb + tg) * TLD + m0 + 8];
                al[2] = smdyn[aL + (rb + tg + 4) * TLD + m0];
                al[3] = smdyn[aL + (rb + tg + 4) * TLD + m0 + 8];
#pragma unroll
                for (int ni = 0; ni < 4; ni++) {
                    mma_bf16(c[mi][ni], ah, bl[ni]);
                    mma_bf16(c[mi][ni], al, bh[ni]);
                    mma_bf16(c[mi][ni], ah, bh[ni]);
                }
            }
        }
        __syncthreads();
    }

    // ---- fused epilogue ----
    const float pt = (mode == 1) ? g_probs[t] : 0.f;
#pragma unroll
    for (int mi = 0; mi < 4; mi++)
#pragma unroll
    for (int half = 0; half < 2; half++) {
        const int r = bm + wm + mi * 16 + half * 8 + g;
        if (r >= M) continue;
#pragma unroll
        for (int ni = 0; ni < 4; ni++) {
            const int lc = wn + ni * 8 + tg * 2;
            const int gc = ny * 128 + lc;
            float v0 = c[mi][ni][half * 2 + 0] + bias[gc];
            float v1 = c[mi][ni][half * 2 + 1] + bias[gc + 1];
            const size_t rb = (size_t)r * 256;
            if (mode == 0) {
                float s0 = 1.f / (1.f + expf(-v0));
                float s1 = 1.f / (1.f + expf(-v1));
                if (ny < 2) {
                    *reinterpret_cast<float2*>(&g_Z[rb + gc]) = make_float2(s0, s1);
                } else {
                    int hc = gc - 256;
                    float2 h = *reinterpret_cast<const float2*>(&g_H[rb + hc]);
                    uint32_t hi, lo; split_pack(s0 * h.x, s1 * h.y, hi, lo);
                    size_t o = (size_t)(hc >> 1) * NODES + r;
                    g_HRhi[o] = hi; g_HRlo[o] = lo;
                }
            } else if (mode == 1) {
                float2 z = *reinterpret_cast<const float2*>(&g_Z[rb + gc]);
                float2 h = *reinterpret_cast<const float2*>(&g_H[rb + gc]);
                float hn0 = z.x * h.x + (1.f - z.x) * tanhf(v0);
                float hn1 = z.y * h.y + (1.f - z.y) * tanhf(v1);
                size_t o = (size_t)(gc >> 1) * NODES + r;
                if (!last) {
                    *reinterpret_cast<float2*>(&g_H[rb + gc]) = make_float2(hn0, hn1);
                    uint32_t hi, lo; split_pack(hn0, hn1, hi, lo);
                    g_Hhi[o] = hi; g_Hlo[o] = lo;
                    float2 a = *reinterpret_cast<const float2*>(&g_acc[rb + gc]);
                    a.x += pt * hn0; a.y += pt * hn1;
                    *reinterpret_cast<float2*>(&g_acc[rb + gc]) = a;
                } else {
                    float2 a = *reinterpret_cast<const float2*>(&g_acc[rb + gc]);
                    float a0 = fmaxf(a.x + pt * hn0, 0.f);
                    float a1 = fmaxf(a.y + pt * hn1, 0.f);
                    uint32_t hi, lo; split_pack(a0, a1, hi, lo);
                    g_M0hi[o] = hi; g_M0lo[o] = lo;
                }
            } else if (mode == 4) {
                *reinterpret_cast<float2*>(&g_Z[rb + gc]) =
                    make_float2(fmaxf(v0, 0.f), fmaxf(v1, 0.f));
            } else {
                uint32_t hi, lo; split_pack(fmaxf(v0, 0.f), fmaxf(v1, 0.f), hi, lo);
                size_t o = (size_t)(gc >> 1) * NODES + r;
                if (mode == 2) { g_M1hi[o] = hi; g_M1lo[o] = lo; }
                else           { g_M0hi[o] = hi; g_M0lo[o] = lo; }
            }
        }
    }
}

// ---------------- final projection ----------------
__global__ void k_out(const float* __restrict__ Wo, const float* __restrict__ bo,
                      float* __restrict__ out, int M) {
    int warp = (blockIdx.x * blockDim.x + threadIdx.x) >> 5;
    int lane = threadIdx.x & 31;
    if (warp >= M) return;
    float acc[TSTEPS];
#pragma unroll
    for (int j = 0; j < TSTEPS; j++) acc[j] = 0.f;
    const float* a = g_Z + (size_t)warp * 256;
    for (int k = lane; k < 256; k += 32) {
        float av = a[k];
        const float* wr = Wo + k * TSTEPS;
#pragma unroll
        for (int j = 0; j < TSTEPS; j++) acc[j] += av * wr[j];
    }
#pragma unroll
    for (int off = 16; off > 0; off >>= 1)
#pragma unroll
        for (int j = 0; j < TSTEPS; j++)
            acc[j] += __shfl_xor_sync(0xffffffffu, acc[j], off);
    if (lane == 0) {
        float* o = out + (size_t)warp * TSTEPS;
#pragma unroll
        for (int j = 0; j < TSTEPS; j++) o[j] = acc[j] + bo[j];
    }
}

// ---------------- launch ----------------
extern "C" void kernel_launch(void* const* d_in, const int* in_sizes, int n_in,
                              void* d_out, int out_size) {
    const float* x   = (const float*)d_in[0];
    const void*  ei  = d_in[1];
    const float* w   = (const float*)d_in[2];
    const float *Wz = (const float*)d_in[3],  *bz = (const float*)d_in[4];
    const float *Wlz= (const float*)d_in[5],  *blz= (const float*)d_in[6];
    const float *Wr = (const float*)d_in[7],  *br = (const float*)d_in[8];
    const float *Wlr= (const float*)d_in[9],  *blr= (const float*)d_in[10];
    const float *Wh = (const float*)d_in[11], *bh = (const float*)d_in[12];
    const float *Wlh= (const float*)d_in[13], *blh= (const float*)d_in[14];
    const float *att= (const float*)d_in[15];
    const float *W1 = (const float*)d_in[16], *b1 = (const float*)d_in[17];
    const float *W2 = (const float*)d_in[18], *b2 = (const float*)d_in[19];
    const float *W3 = (const float*)d_in[20], *b3 = (const float*)d_in[21];
    const float *Wo = (const float*)d_in[22], *bo = (const float*)d_in[23];
    float* out = (float*)d_out;

    const int E = in_sizes[2];
    const int N = in_sizes[0] / FT;
    const int nh = N * 256;

    cudaFuncSetAttribute(gemmx, cudaFuncAttributeMaxDynamicSharedMemorySize, SMEM_BYTES);

    k_init<<<(nh + 255) / 256, 256>>>((const int*)ei, N, nh);
    k_deg <<<(E + 255) / 256, 256>>>(ei, w, E);
    {
        int tot = E + N * 36;
        k_normax<<<(tot + 255) / 256, 256>>>(x, ei, w, E, N);
    }
    {
        long long tot = (long long)E * 36;
        k_axedge<<<(unsigned)((tot + 255) / 256), 256>>>(x, ei, E);
    }
    k_axsplit<<<(N * TSTEPS + 255) / 256, 256>>>(N);
    k_probs<<<1, 32>>>(att);

    const int bb = (145 * 256 + 255) / 256;
    k_buildB<<<bb, 256>>>(Wz, Wlz, bz, blz, 0);
    k_buildB<<<bb, 256>>>(Wr, Wlr, br, blr, 1);
    k_buildB<<<bb, 256>>>(Wh, Wlh, bh, blh, 2);
    k_splitW<<<(3 * 128 * 256 + 255) / 256, 256>>>(W1, W2, W3);

    const int gbm = (N + 127) / 128;
    for (int t = 0; t < TSTEPS; t++) {
        gemmx<<<dim3(4, gbm), 256, SMEM_BYTES>>>(nullptr, N, 0, t, 0);
        gemmx<<<dim3(2, gbm), 256, SMEM_BYTES>>>(nullptr, N, 1, t, t == TSTEPS - 1);
    }
    gemmx<<<dim3(2, gbm), 256, SMEM_BYTES>>>(b1, N, 2, 0, 0);
    gemmx<<<dim3(2, gbm), 256, SMEM_BYTES>>>(b2, N, 3, 0, 0);
    gemmx<<<dim3(2, gbm), 256, SMEM_BYTES>>>(b3, N, 4, 0, 0);

    k_out<<<(N * 32 + 255) / 256, 256>>>(Wo, bo, out, N);
}